// round 4
// baseline (speedup 1.0000x reference)
#include <cuda_runtime.h>
#include <cstdint>

#define ROWS   4096
#define FDIM   16384
#define BINS   128
#define NFEAT  257            // 128 counts + 129 boundaries
#define FPAD   260            // padded row length of feats
#define OUT    64
#define HB     512
#define NW     (HB / 32)      // 16 warps
#define GROWS  16             // rows per GEMM CTA
#define WPITCH 68             // padded WT row pitch (floats), 16B-aligned, bank-friendly

// Inter-kernel scratch (no allocs allowed)
__device__ __align__(16) float g_feats[ROWS * FPAD];

__device__ __forceinline__ uint32_t smem_u32(const void* p) {
    uint32_t a;
    asm("{ .reg .u64 t; cvta.to.shared.u64 t, %1; cvt.u32.u64 %0, t; }" : "=r"(a) : "l"(p));
    return a;
}

// ---------------------------------------------------------------------------
// Kernel 1: TMA bulk row -> smem, min/max, histogram, feats -> global.
// 3 CTAs/SM (74 KB smem each), one DRAM pass over x.
// ---------------------------------------------------------------------------
__global__ __launch_bounds__(HB, 3) void hist_kernel(const float* __restrict__ x) {
    extern __shared__ __align__(16) float sdata[];      // 16384 floats = 64 KB

    __shared__ unsigned int hist[NW * BINS];            // 8 KB
    __shared__ float s_red[2 * NW];
    __shared__ float s_mnw[2];
    __shared__ __align__(8) unsigned long long mbar;

    const int row  = blockIdx.x;
    const int tid  = threadIdx.x;
    const int warp = tid >> 5;
    const int lane = tid & 31;

    // zero per-warp histograms
    #pragma unroll
    for (int k = 0; k < (NW * BINS) / HB; k++)
        hist[tid + k * HB] = 0u;

    const uint32_t mbar_a = smem_u32(&mbar);
    const uint32_t data_a = smem_u32(sdata);

    if (tid == 0) {
        asm volatile("mbarrier.init.shared.b64 [%0], 1;" :: "r"(mbar_a) : "memory");
        asm volatile("fence.proxy.async.shared::cta;" ::: "memory");
    }
    __syncthreads();

    if (tid == 0) {
        asm volatile("mbarrier.arrive.expect_tx.shared.b64 _, [%0], %1;"
                     :: "r"(mbar_a), "r"(FDIM * 4) : "memory");
        const float* src = x + (size_t)row * FDIM;
        asm volatile("cp.async.bulk.shared::cta.global.mbarrier::complete_tx::bytes "
                     "[%0], [%1], %2, [%3];"
                     :: "r"(data_a), "l"(src), "r"(FDIM * 4), "r"(mbar_a) : "memory");
    }

    // wait (parity 0)
    {
        uint32_t done;
        asm volatile("{\n\t.reg .pred p;\n\t"
                     "mbarrier.try_wait.parity.acquire.cta.shared::cta.b64 p, [%1], 0;\n\t"
                     "selp.b32 %0, 1, 0, p;\n\t}"
                     : "=r"(done) : "r"(mbar_a) : "memory");
        while (!done) {
            asm volatile("{\n\t.reg .pred p;\n\t"
                         "mbarrier.try_wait.parity.acquire.cta.shared::cta.b64 p, [%1], 0, 0x989680;\n\t"
                         "selp.b32 %0, 1, 0, p;\n\t}"
                         : "=r"(done) : "r"(mbar_a) : "memory");
        }
    }

    const float4* sd4 = reinterpret_cast<const float4*>(sdata);

    // pass 1: min/max
    float mn, mx;
    {
        float4 v0 = sd4[tid];
        mn = fminf(fminf(v0.x, v0.y), fminf(v0.z, v0.w));
        mx = fmaxf(fmaxf(v0.x, v0.y), fmaxf(v0.z, v0.w));
        #pragma unroll
        for (int k = 1; k < 8; k++) {
            float4 v = sd4[tid + k * HB];
            mn = fminf(mn, fminf(fminf(v.x, v.y), fminf(v.z, v.w)));
            mx = fmaxf(mx, fmaxf(fmaxf(v.x, v.y), fmaxf(v.z, v.w)));
        }
    }
    #pragma unroll
    for (int o = 16; o > 0; o >>= 1) {
        mn = fminf(mn, __shfl_xor_sync(0xffffffffu, mn, o));
        mx = fmaxf(mx, __shfl_xor_sync(0xffffffffu, mx, o));
    }
    if (lane == 0) { s_red[warp] = mn; s_red[NW + warp] = mx; }
    __syncthreads();
    if (tid == 0) {
        float m = s_red[0], M = s_red[NW];
        #pragma unroll
        for (int i = 1; i < NW; i++) {
            m = fminf(m, s_red[i]);
            M = fmaxf(M, s_red[NW + i]);
        }
        s_mnw[0] = m;
        s_mnw[1] = M - m;
    }
    __syncthreads();

    const float row_mn = s_mnw[0];
    const float width  = s_mnw[1];
    const float invw   = 128.0f / ((width == 0.0f) ? 1.0f : width);
    const float nmn    = -row_mn * invw;

    // pass 2: binning into per-warp private histogram.
    // v >= mn guarantees fma >= -1ulp, so int-trunc == floor + lower clamp.
    unsigned int* h = &hist[warp * BINS];
    #pragma unroll
    for (int k = 0; k < 8; k++) {
        float4 v = sd4[tid + k * HB];
        float vals[4] = {v.x, v.y, v.z, v.w};
        #pragma unroll
        for (int e = 0; e < 4; e++) {
            int b = (int)__fmaf_rn(vals[e], invw, nmn);
            b = min(b, BINS - 1);
            atomicAdd(&h[b], 1u);
        }
    }
    __syncthreads();

    // feats: counts/16384, boundaries, zero pad
    float* fr = &g_feats[(size_t)row * FPAD];
    if (tid < BINS) {
        unsigned int c = 0;
        #pragma unroll
        for (int w = 0; w < NW; w++) c += hist[w * BINS + tid];
        fr[tid] = (float)c * (1.0f / 16384.0f);
    } else if (tid < NFEAT) {
        int k = tid - BINS;                        // 0..128
        float t = (float)k * (1.0f / 128.0f);      // exact
        fr[tid] = row_mn + t * width;
    } else if (tid < FPAD) {
        fr[tid] = 0.0f;
    }
}

// ---------------------------------------------------------------------------
// Kernel 2: out = feats @ W^T + b. Each CTA transposes W into smem once
// (coalesced global read), then 16 rows x 64 outputs per CTA.
// ---------------------------------------------------------------------------
__global__ __launch_bounds__(256) void gemm_kernel(const float* __restrict__ W,
                                                   const float* __restrict__ bias,
                                                   float* __restrict__ out) {
    extern __shared__ __align__(16) float gsm[];
    float* sWT = gsm;                       // [FPAD][WPITCH] = 260*68 floats
    float* sf  = gsm + FPAD * WPITCH;       // [GROWS][FPAD]

    const int tid  = threadIdx.x;
    const int row0 = blockIdx.x * GROWS;

    // transpose W[64][257] -> sWT[i][j], coalesced global reads
    for (int n = tid; n < OUT * NFEAT; n += 256) {
        int j = n / NFEAT;
        int i = n - j * NFEAT;
        sWT[i * WPITCH + j] = W[n];
    }
    // zero pad rows 257..259
    for (int n = tid; n < (FPAD - NFEAT) * OUT; n += 256) {
        int i = NFEAT + (n >> 6);
        int j = n & 63;
        sWT[i * WPITCH + j] = 0.0f;
    }
    // load feats block (pad cols already zero in g_feats)
    const float* src = &g_feats[(size_t)row0 * FPAD];
    for (int k = tid; k < GROWS * FPAD; k += 256) sf[k] = src[k];
    __syncthreads();

    const int r  = tid >> 4;   // local row 0..15
    const int j4 = tid & 15;   // output float4 group

    const float* f = &sf[r * FPAD];
    float4 acc = make_float4(0.f, 0.f, 0.f, 0.f);
    #pragma unroll 4
    for (int i = 0; i < FPAD; i++) {
        float  fv = f[i];
        float4 wv = *reinterpret_cast<const float4*>(&sWT[i * WPITCH + j4 * 4]);
        acc.x += fv * wv.x;
        acc.y += fv * wv.y;
        acc.z += fv * wv.z;
        acc.w += fv * wv.w;
    }
    float4 bb = reinterpret_cast<const float4*>(bias)[j4];
    float4 o  = make_float4(acc.x + bb.x, acc.y + bb.y, acc.z + bb.z, acc.w + bb.w);
    reinterpret_cast<float4*>(out)[(size_t)(row0 + r) * (OUT / 4) + j4] = o;
}

// ---------------------------------------------------------------------------
extern "C" void kernel_launch(void* const* d_in, const int* in_sizes, int n_in,
                              void* d_out, int out_size) {
    const float* x    = (const float*)d_in[0];   // [4096, 16384]
    const float* W    = (const float*)d_in[1];   // [64, 257]
    const float* bias = (const float*)d_in[2];   // [64]
    float* out = (float*)d_out;                  // [4096, 64]

    const int hist_smem = FDIM * 4;                              // 64 KB dynamic
    const int gemm_smem = (FPAD * WPITCH + GROWS * FPAD) * 4;    // ~87 KB dynamic
    cudaFuncSetAttribute(hist_kernel, cudaFuncAttributeMaxDynamicSharedMemorySize, hist_smem);
    cudaFuncSetAttribute(gemm_kernel, cudaFuncAttributeMaxDynamicSharedMemorySize, gemm_smem);

    hist_kernel<<<ROWS, HB, hist_smem>>>(x);
    gemm_kernel<<<ROWS / GROWS, 256, gemm_smem>>>(W, bias, out);
}